// round 5
// baseline (speedup 1.0000x reference)
#include <cuda_runtime.h>
#include <cuda_bf16.h>
#include <cstdint>

// ---------------- constants ----------------
#define BATCH 4
#define T_TOTAL 35968706LL          // sum of all hypernet parameter counts
#define NT4 (T_TOTAL / 4)           // 8,992,176 full float4 columns; remainder 2

// ---------------- device scratch (no allocation allowed) ----------------
__device__ float g_bufA[4 * 4 * 112 * 112];   // 200,704 floats
__device__ float g_bufB[4 * 8 * 56 * 56];     // 100,352 floats
__device__ float g_bufC[100352];              // partials scratch
__device__ float g_q[BATCH * 16];             // quantized latents for the big GEMM

// ---------------- templated 4x4 stride-2 pad-1 conv (full unroll) ----------------
// SPLIT > 1: split the Cin reduction into SPLIT partial outputs, layout [s][b][co][oh][ow].
template<int CIN, int COUT, int HIN, int HOUT, bool ACT, int SPLIT, bool ADD_BIAS>
__global__ void __launch_bounds__(256) convT(const float* __restrict__ in,
                                             const float* __restrict__ w,
                                             const float* __restrict__ bias,
                                             float* __restrict__ out) {
    constexpr int CPS = CIN / SPLIT;
    int tid = blockIdx.x * 256 + threadIdx.x;
    constexpr int TOTAL = BATCH * COUT * HOUT * HOUT * SPLIT;
    if (tid >= TOTAL) return;

    int ow = tid % HOUT;
    int oh = (tid / HOUT) % HOUT;
    int co = (tid / (HOUT * HOUT)) % COUT;
    int b  = (tid / (HOUT * HOUT * COUT)) % BATCH;
    int s  = tid / (HOUT * HOUT * COUT * BATCH);

    float acc = ADD_BIAS ? bias[co] : 0.0f;
    int ih0 = oh * 2 - 1;
    int iw0 = ow * 2 - 1;

    const float* wbase = w + ((size_t)co * CIN + s * CPS) * 16;
    const float* ibase = in + ((size_t)b * CIN + s * CPS) * HIN * HIN;

    #pragma unroll
    for (int ci = 0; ci < CPS; ci++) {
        const float* ip = ibase + (size_t)ci * HIN * HIN;
        const float* wp = wbase + ci * 16;
        #pragma unroll
        for (int kh = 0; kh < 4; kh++) {
            int ih = ih0 + kh;
            bool rowok = (unsigned)ih < (unsigned)HIN;
            #pragma unroll
            for (int kw = 0; kw < 4; kw++) {
                int iw = iw0 + kw;
                bool ok = rowok && ((unsigned)iw < (unsigned)HIN);
                float v = ok ? __ldg(ip + (size_t)ih * HIN + iw) : 0.0f;
                acc = fmaf(v, __ldg(wp + kh * 4 + kw), acc);
            }
        }
    }
    if (ACT) acc = (acc >= 0.0f) ? acc : 0.01f * acc;
    out[tid] = acc;
}

// ---------------- finalize: sum SPLIT partials + bias + LeakyReLU ----------------
template<int N, int COUT, int HW, int SPLIT>
__global__ void __launch_bounds__(256) finT(const float* __restrict__ p,
                                            const float* __restrict__ bias,
                                            float* __restrict__ out) {
    int i = blockIdx.x * 256 + threadIdx.x;
    if (i >= N) return;
    float s = bias[(i / HW) % COUT];
    #pragma unroll
    for (int j = 0; j < SPLIT; j++) s += p[(size_t)j * N + i];
    out[i] = (s >= 0.0f) ? s : 0.01f * s;
}

// ---------------- head: sum conv5 partials(4) + bias + avgpool + fc1 + fc2 + VQ + loss
// conv5 partials layout: p[s][b][co][49], s in 0..3, no bias applied yet.
__global__ void head_k(const float* __restrict__ p,
                       const float* __restrict__ cb5,
                       const float* __restrict__ fc1_w, const float* __restrict__ fc1_b,
                       const float* __restrict__ fc2_w, const float* __restrict__ fc2_b,
                       const float* __restrict__ emb,
                       float* __restrict__ loss_out) {
    __shared__ float pooled[BATCH * 64];
    __shared__ float h[BATCH * 16];
    __shared__ float e[BATCH * 16];
    __shared__ float qv[BATCH * 16];
    int tid = threadIdx.x;   // 256 threads
    constexpr int N5 = BATCH * 64 * 49;  // 12544 per split

    // pooled[b][c] = mean over 49 of sum_s partial_s + bias
    {
        int b = tid / 64, c = tid % 64;
        float sum = 0.0f;
        #pragma unroll
        for (int s = 0; s < 4; s++) {
            const float* ps = p + (size_t)s * N5 + (size_t)(b * 64 + c) * 49;
            #pragma unroll
            for (int i = 0; i < 49; i++) sum += ps[i];
        }
        pooled[b * 64 + c] = sum * (1.0f / 49.0f) + cb5[c];
    }
    __syncthreads();

    // fc1: [4,64] @ [16,64]^T + b, LeakyReLU
    if (tid < 64) {
        int b = tid / 16, i = tid % 16;
        float s = fc1_b[i];
        #pragma unroll
        for (int c = 0; c < 64; c++) s += pooled[b * 64 + c] * fc1_w[i * 64 + c];
        h[b * 16 + i] = (s >= 0.0f) ? s : 0.01f * s;
    }
    __syncthreads();

    // fc2: [4,16] @ [16,16]^T + b
    if (tid < 64) {
        int b = tid / 16, j = tid % 16;
        float s = fc2_b[j];
        #pragma unroll
        for (int i = 0; i < 16; i++) s += h[b * 16 + i] * fc2_w[j * 16 + i];
        e[b * 16 + j] = s;
    }
    __syncthreads();

    // VQ nearest codebook (DICT = 4)
    if (tid < BATCH) {
        int b = tid;
        float best = 3.402823e38f;
        int bi = 0;
        for (int j = 0; j < 4; j++) {
            float d = 0.0f;
            #pragma unroll
            for (int k = 0; k < 16; k++) {
                float diff = e[b * 16 + k] - emb[j * 16 + k];
                d += diff * diff;
            }
            if (d < best) { best = d; bi = j; }
        }
        #pragma unroll
        for (int k = 0; k < 16; k++) qv[b * 16 + k] = emb[bi * 16 + k];
    }
    __syncthreads();

    if (tid == 0) {
        float s = 0.0f;
        #pragma unroll
        for (int n = 0; n < 64; n++) {
            float d = qv[n] - e[n];
            s += d * d;
        }
        *loss_out = 1.25f * (s * (1.0f / 64.0f));   // q_lat + 0.25 * e_lat
        #pragma unroll
        for (int n = 0; n < 64; n++) g_q[n] = qv[n];
    }
}

// ---------------- big GEMM: flat = q @ W_all, [4,16] x [16, T_TOTAL] ----------------
// Pure HBM streaming. Hybrid vectorization: row k byte offset k*T_TOTAL*4 is
// ≡0 mod 16 for even k (float4 path) and ≡8 mod 16 for odd k (2x float2 path).
// Each thread handles 4 consecutive columns; one extra thread covers the 2-col tail.
__global__ void __launch_bounds__(256) hyper_gemm_k(const float* __restrict__ W,
                                                    float* __restrict__ out) {
    __shared__ float qs[64];
    if (threadIdx.x < 64) qs[threadIdx.x] = g_q[threadIdx.x];
    __syncthreads();

    long long t = (long long)blockIdx.x * blockDim.x + threadIdx.x;
    if (t > NT4) return;
    long long c0 = 4LL * t;

    if (t == NT4) {
        // tail: final 2 columns (8B-aligned in every row)
        float2 w[16];
        #pragma unroll
        for (int k = 0; k < 16; k++)
            w[k] = *(const float2*)(W + (size_t)k * T_TOTAL + c0);
        #pragma unroll
        for (int b = 0; b < 4; b++) {
            float ax = 0.0f, ay = 0.0f;
            #pragma unroll
            for (int k = 0; k < 16; k++) {
                float qk = qs[b * 16 + k];
                ax = fmaf(qk, w[k].x, ax);
                ay = fmaf(qk, w[k].y, ay);
            }
            *(float2*)(out + (size_t)b * T_TOTAL + c0) = make_float2(ax, ay);
        }
        return;
    }

    float4 w[16];
    #pragma unroll
    for (int k = 0; k < 16; k++) {
        const float* p = W + (size_t)k * T_TOTAL + c0;
        if (k & 1) {
            float2 a = *(const float2*)p;
            float2 c = *(const float2*)(p + 2);
            w[k] = make_float4(a.x, a.y, c.x, c.y);
        } else {
            w[k] = *(const float4*)p;
        }
    }

    #pragma unroll
    for (int b = 0; b < 4; b++) {
        float a0 = 0.0f, a1 = 0.0f, a2 = 0.0f, a3 = 0.0f;
        #pragma unroll
        for (int k = 0; k < 16; k++) {
            float qk = qs[b * 16 + k];
            a0 = fmaf(qk, w[k].x, a0);
            a1 = fmaf(qk, w[k].y, a1);
            a2 = fmaf(qk, w[k].z, a2);
            a3 = fmaf(qk, w[k].w, a3);
        }
        float* po = out + (size_t)b * T_TOTAL + c0;
        if (b & 1) {
            *(float2*)po       = make_float2(a0, a1);
            *(float2*)(po + 2) = make_float2(a2, a3);
        } else {
            *(float4*)po = make_float4(a0, a1, a2, a3);
        }
    }
}

// ---------------- launch ----------------
extern "C" void kernel_launch(void* const* d_in, const int* in_sizes, int n_in,
                              void* d_out, int out_size) {
    const float* rgb   = (const float*)d_in[0];
    const float* cw1   = (const float*)d_in[1];
    const float* cb1   = (const float*)d_in[2];
    const float* cw2   = (const float*)d_in[3];
    const float* cb2   = (const float*)d_in[4];
    const float* cw3   = (const float*)d_in[5];
    const float* cb3   = (const float*)d_in[6];
    const float* cw4   = (const float*)d_in[7];
    const float* cb4   = (const float*)d_in[8];
    const float* cw5   = (const float*)d_in[9];
    const float* cb5   = (const float*)d_in[10];
    const float* fc1_w = (const float*)d_in[11];
    const float* fc1_b = (const float*)d_in[12];
    const float* fc2_w = (const float*)d_in[13];
    const float* fc2_b = (const float*)d_in[14];
    const float* emb   = (const float*)d_in[15];
    const float* W_all = (const float*)d_in[16];

    float* out = (float*)d_out;
    float* loss_ptr = out + (size_t)out_size - 1;   // flat first, loss scalar last

    float* bufA;  cudaGetSymbolAddress((void**)&bufA, g_bufA);
    float* bufB;  cudaGetSymbolAddress((void**)&bufB, g_bufB);
    float* bufC;  cudaGetSymbolAddress((void**)&bufC, g_bufC);

    // conv1: 3->4,  224->112, act, out bufA (200704)
    convT<3, 4, 224, 112, true, 1, true><<<784, 256>>>(rgb, cw1, cb1, bufA);
    // conv2: 4->8,  112->56,  act, out bufB (100352)
    convT<4, 8, 112, 56, true, 1, true><<<392, 256>>>(bufA, cw2, cb2, bufB);
    // conv3: 8->16, 56->28, SPLIT=2 partials -> bufC (100352)
    convT<8, 16, 56, 28, false, 2, false><<<392, 256>>>(bufB, cw3, (const float*)nullptr, bufC);
    // fin3: sum 2 + bias + lrelu -> bufA (50176)
    finT<4 * 16 * 28 * 28, 16, 28 * 28, 2><<<196, 256>>>(bufC, cb3, bufA);
    // conv4: 16->32, 28->14, SPLIT=4 partials -> bufB (100352)
    convT<16, 32, 28, 14, false, 4, false><<<392, 256>>>(bufA, cw4, (const float*)nullptr, bufB);
    // fin4: sum 4 + bias + lrelu -> bufC (25088)
    finT<4 * 32 * 14 * 14, 32, 14 * 14, 4><<<98, 256>>>(bufB, cb4, bufC);
    // conv5: 32->64, 14->7, NO activation, SPLIT=4, no bias -> bufA (50176)
    convT<32, 64, 14, 7, false, 4, false><<<196, 256>>>(bufC, cw5, (const float*)nullptr, bufA);

    // head: sum 4 partials + bias + pool + fc1 + fc2 + VQ + loss -> g_q, loss
    head_k<<<1, 256>>>(bufA, cb5, fc1_w, fc1_b, fc2_w, fc2_b, emb, loss_ptr);

    // big streaming GEMM: flat = q @ W_all  (NT4 + 1 threads)
    { long long nthreads = NT4 + 1;
      unsigned nblk = (unsigned)((nthreads + 255) / 256);
      hyper_gemm_k<<<nblk, 256>>>(W_all, out); }
}

// round 6
// speedup vs baseline: 1.0852x; 1.0852x over previous
#include <cuda_runtime.h>
#include <cuda_bf16.h>
#include <cstdint>

// ---------------- constants ----------------
#define BATCH 4
#define T_TOTAL 35968706LL          // sum of all hypernet parameter counts
#define T2 (T_TOTAL / 2)            // 17,984,353 float2 columns (T_TOTAL is even)

// ---------------- device scratch (no allocation allowed) ----------------
__device__ float g_bufA[4 * 4 * 112 * 112];   // 200,704 floats (largest intermediate)
__device__ float g_bufB[4 * 8 * 56 * 56];     // 100,352 floats
__device__ float g_q[BATCH * 16];             // quantized latents for the big GEMM

// ---------------- templated 4x4 stride-2 pad-1 conv (full unroll) ----------------
// TPB: threads per block (small blocks spread tiny grids across all 148 SMs).
// SPLIT > 1: split the Cin reduction into SPLIT partial outputs [s][b][co][oh][ow].
template<int CIN, int COUT, int HIN, int HOUT, bool ACT, int SPLIT, bool ADD_BIAS, int TPB>
__global__ void __launch_bounds__(TPB) convT(const float* __restrict__ in,
                                             const float* __restrict__ w,
                                             const float* __restrict__ bias,
                                             float* __restrict__ out) {
    constexpr int CPS = CIN / SPLIT;
    int tid = blockIdx.x * TPB + threadIdx.x;
    constexpr int TOTAL = BATCH * COUT * HOUT * HOUT * SPLIT;
    if (tid >= TOTAL) return;

    int ow = tid % HOUT;
    int oh = (tid / HOUT) % HOUT;
    int co = (tid / (HOUT * HOUT)) % COUT;
    int b  = (tid / (HOUT * HOUT * COUT)) % BATCH;
    int s  = tid / (HOUT * HOUT * COUT * BATCH);

    float acc = ADD_BIAS ? bias[co] : 0.0f;
    int ih0 = oh * 2 - 1;
    int iw0 = ow * 2 - 1;

    const float* wbase = w + ((size_t)co * CIN + s * CPS) * 16;
    const float* ibase = in + ((size_t)b * CIN + s * CPS) * HIN * HIN;

    #pragma unroll
    for (int ci = 0; ci < CPS; ci++) {
        const float* ip = ibase + (size_t)ci * HIN * HIN;
        const float* wp = wbase + ci * 16;
        #pragma unroll
        for (int kh = 0; kh < 4; kh++) {
            int ih = ih0 + kh;
            bool rowok = (unsigned)ih < (unsigned)HIN;
            #pragma unroll
            for (int kw = 0; kw < 4; kw++) {
                int iw = iw0 + kw;
                bool ok = rowok && ((unsigned)iw < (unsigned)HIN);
                float v = ok ? __ldg(ip + (size_t)ih * HIN + iw) : 0.0f;
                acc = fmaf(v, __ldg(wp + kh * 4 + kw), acc);
            }
        }
    }
    if (ACT) acc = (acc >= 0.0f) ? acc : 0.01f * acc;
    out[tid] = acc;
}

// ---------------- head: sum conv5 partials + bias + avgpool + fc1 + fc2 + VQ + loss ----
// conv5 partials layout: p[s][b][co][49], s in {0,1}, no bias applied yet.
__global__ void head_k(const float* __restrict__ p,
                       const float* __restrict__ cb5,
                       const float* __restrict__ fc1_w, const float* __restrict__ fc1_b,
                       const float* __restrict__ fc2_w, const float* __restrict__ fc2_b,
                       const float* __restrict__ emb,
                       float* __restrict__ loss_out) {
    __shared__ float pooled[BATCH * 64];
    __shared__ float h[BATCH * 16];
    __shared__ float e[BATCH * 16];
    __shared__ float qv[BATCH * 16];
    int tid = threadIdx.x;   // 256 threads

    // pooled[b][c] = mean over 49 of (partial0 + partial1) + bias
    {
        int b = tid / 64, c = tid % 64;
        const float* p0 = p + (size_t)(0 * BATCH * 64 + b * 64 + c) * 49;
        const float* p1 = p + (size_t)(1 * BATCH * 64 + b * 64 + c) * 49;
        float sum = 0.0f;
        #pragma unroll
        for (int i = 0; i < 49; i++) sum += p0[i] + p1[i];
        pooled[b * 64 + c] = sum * (1.0f / 49.0f) + cb5[c];
    }
    __syncthreads();

    // fc1: [4,64] @ [16,64]^T + b, LeakyReLU
    if (tid < 64) {
        int b = tid / 16, i = tid % 16;
        float s = fc1_b[i];
        #pragma unroll
        for (int c = 0; c < 64; c++) s += pooled[b * 64 + c] * fc1_w[i * 64 + c];
        h[b * 16 + i] = (s >= 0.0f) ? s : 0.01f * s;
    }
    __syncthreads();

    // fc2: [4,16] @ [16,16]^T + b
    if (tid < 64) {
        int b = tid / 16, j = tid % 16;
        float s = fc2_b[j];
        #pragma unroll
        for (int i = 0; i < 16; i++) s += h[b * 16 + i] * fc2_w[j * 16 + i];
        e[b * 16 + j] = s;
    }
    __syncthreads();

    // VQ nearest codebook (DICT = 4)
    if (tid < BATCH) {
        int b = tid;
        float best = 3.402823e38f;
        int bi = 0;
        for (int j = 0; j < 4; j++) {
            float d = 0.0f;
            #pragma unroll
            for (int k = 0; k < 16; k++) {
                float diff = e[b * 16 + k] - emb[j * 16 + k];
                d += diff * diff;
            }
            if (d < best) { best = d; bi = j; }
        }
        #pragma unroll
        for (int k = 0; k < 16; k++) qv[b * 16 + k] = emb[bi * 16 + k];
    }
    __syncthreads();

    if (tid == 0) {
        float s = 0.0f;
        #pragma unroll
        for (int n = 0; n < 64; n++) {
            float d = qv[n] - e[n];
            s += d * d;
        }
        *loss_out = 1.25f * (s * (1.0f / 64.0f));   // q_lat + 0.25 * e_lat
        #pragma unroll
        for (int n = 0; n < 64; n++) g_q[n] = qv[n];
    }
}

// ---------------- big GEMM: flat = q @ W_all, [4,16] x [16, T_TOTAL] ----------------
// Pure HBM streaming: read 2.30 GB of W, write 0.575 GB of output.
// float2 vectorized (rows are 8B-aligned; T_TOTAL % 4 == 2 forbids float4 per-row).
// Proven 6.47 TB/s effective in R2 — do not touch.
__global__ void __launch_bounds__(256) hyper_gemm_k(const float* __restrict__ W,
                                                    float* __restrict__ out) {
    __shared__ float qs[64];
    if (threadIdx.x < 64) qs[threadIdx.x] = g_q[threadIdx.x];
    __syncthreads();

    long long t2 = (long long)blockIdx.x * blockDim.x + threadIdx.x;
    if (t2 >= T2) return;

    float2 w[16];
    #pragma unroll
    for (int k = 0; k < 16; k++) {
        w[k] = __ldg((const float2*)(W + (size_t)k * T_TOTAL) + t2);
    }

    #pragma unroll
    for (int b = 0; b < 4; b++) {
        float ax = 0.0f, ay = 0.0f;
        #pragma unroll
        for (int k = 0; k < 16; k++) {
            float qk = qs[b * 16 + k];
            ax = fmaf(qk, w[k].x, ax);
            ay = fmaf(qk, w[k].y, ay);
        }
        ((float2*)(out + (size_t)b * T_TOTAL))[t2] = make_float2(ax, ay);
    }
}

// ---------------- launch ----------------
extern "C" void kernel_launch(void* const* d_in, const int* in_sizes, int n_in,
                              void* d_out, int out_size) {
    const float* rgb   = (const float*)d_in[0];
    const float* cw1   = (const float*)d_in[1];
    const float* cb1   = (const float*)d_in[2];
    const float* cw2   = (const float*)d_in[3];
    const float* cb2   = (const float*)d_in[4];
    const float* cw3   = (const float*)d_in[5];
    const float* cb3   = (const float*)d_in[6];
    const float* cw4   = (const float*)d_in[7];
    const float* cb4   = (const float*)d_in[8];
    const float* cw5   = (const float*)d_in[9];
    const float* cb5   = (const float*)d_in[10];
    const float* fc1_w = (const float*)d_in[11];
    const float* fc1_b = (const float*)d_in[12];
    const float* fc2_w = (const float*)d_in[13];
    const float* fc2_b = (const float*)d_in[14];
    const float* emb   = (const float*)d_in[15];
    const float* W_all = (const float*)d_in[16];

    float* out = (float*)d_out;
    float* loss_ptr = out + (size_t)out_size - 1;   // flat first, loss scalar last

    float* bufA;  cudaGetSymbolAddress((void**)&bufA, g_bufA);
    float* bufB;  cudaGetSymbolAddress((void**)&bufB, g_bufB);

    // conv1: 3->4,  224->112, act, out bufA (200704 threads) — plenty of blocks at 256
    convT<3, 4, 224, 112, true, 1, true, 256><<<784, 256>>>(rgb, cw1, cb1, bufA);
    // conv2: 4->8,  112->56, act, out bufB (100352 threads)
    convT<4, 8, 112, 56, true, 1, true, 256><<<392, 256>>>(bufA, cw2, cb2, bufB);
    // conv3: 8->16, 56->28, act, out bufA (50176 threads) — 64-thread blocks: 784 blocks
    convT<8, 16, 56, 28, true, 1, true, 64><<<784, 64>>>(bufB, cw3, cb3, bufA);
    // conv4: 16->32, 28->14, act, out bufB (25088 threads) — 64-thread blocks: 392 blocks
    convT<16, 32, 28, 14, true, 1, true, 64><<<392, 64>>>(bufA, cw4, cb4, bufB);
    // conv5: 32->64, 14->7, NO act, SPLIT=2 ci-halves, no bias (head adds it)
    // out bufA: [2][4][64][49] = 25088 threads — 64-thread blocks: 392 blocks
    convT<32, 64, 14, 7, false, 2, false, 64><<<392, 64>>>(bufB, cw5, (const float*)nullptr, bufA);

    // head: partial-sum + bias + pool + fc1 + fc2 + VQ + loss -> writes g_q and loss
    head_k<<<1, 256>>>(bufA, cb5, fc1_w, fc1_b, fc2_w, fc2_b, emb, loss_ptr);

    // big streaming GEMM: flat = q @ W_all
    { const int TPB = 256;
      long long nblk = (T2 + TPB - 1) / TPB;
      hyper_gemm_k<<<(unsigned)nblk, TPB>>>(W_all, out); }
}

// round 7
// speedup vs baseline: 1.0967x; 1.0106x over previous
#include <cuda_runtime.h>
#include <cuda_bf16.h>
#include <cstdint>

// ---------------- constants ----------------
#define BATCH 4
#define T_TOTAL 35968706LL          // sum of all hypernet parameter counts
#define T2 (T_TOTAL / 2)            // 17,984,353 float2 columns (T_TOTAL is even)

// ---------------- device scratch (no allocation allowed) ----------------
__device__ float g_bufA[4 * 4 * 112 * 112];   // 200,704 floats (largest intermediate)
__device__ float g_bufB[4 * 8 * 56 * 56];     // 100,352 floats
__device__ float g_q[BATCH * 16];             // quantized latents for the big GEMM

// ---------------- templated 4x4 stride-2 pad-1 conv (full unroll) ----------------
// SPLIT > 1: the Cin reduction is split across SPLIT ADJACENT LANES of a warp and
// reduced with __shfl_xor_sync — no partials buffer, no finalize kernel.
// Thread t: output o = t / SPLIT, slice s = t % SPLIT (SPLIT divides 32).
template<int CIN, int COUT, int HIN, int HOUT, bool ACT, int SPLIT, int TPB>
__global__ void __launch_bounds__(TPB) convT(const float* __restrict__ in,
                                             const float* __restrict__ w,
                                             const float* __restrict__ bias,
                                             float* __restrict__ out) {
    constexpr int CPS = CIN / SPLIT;
    int tid = blockIdx.x * TPB + threadIdx.x;
    constexpr int TOTAL = BATCH * COUT * HOUT * HOUT * SPLIT;
    if (tid >= TOTAL) return;   // grids are exact multiples; never splits a warp

    int s = tid % SPLIT;
    int o = tid / SPLIT;
    int ow = o % HOUT;
    int oh = (o / HOUT) % HOUT;
    int co = (o / (HOUT * HOUT)) % COUT;
    int b  = o / (HOUT * HOUT * COUT);

    float acc = 0.0f;
    int ih0 = oh * 2 - 1;
    int iw0 = ow * 2 - 1;

    const float* wbase = w + ((size_t)co * CIN + s * CPS) * 16;
    const float* ibase = in + ((size_t)b * CIN + s * CPS) * HIN * HIN;

    #pragma unroll
    for (int ci = 0; ci < CPS; ci++) {
        const float* ip = ibase + (size_t)ci * HIN * HIN;
        const float* wp = wbase + ci * 16;
        #pragma unroll
        for (int kh = 0; kh < 4; kh++) {
            int ih = ih0 + kh;
            bool rowok = (unsigned)ih < (unsigned)HIN;
            #pragma unroll
            for (int kw = 0; kw < 4; kw++) {
                int iw = iw0 + kw;
                bool ok = rowok && ((unsigned)iw < (unsigned)HIN);
                float v = ok ? __ldg(ip + (size_t)ih * HIN + iw) : 0.0f;
                acc = fmaf(v, __ldg(wp + kh * 4 + kw), acc);
            }
        }
    }

    // in-warp reduction across the SPLIT slices (adjacent lanes)
    #pragma unroll
    for (int off = SPLIT / 2; off > 0; off >>= 1)
        acc += __shfl_xor_sync(0xffffffffu, acc, off);

    if (s == 0) {
        acc += bias[co];
        if (ACT) acc = (acc >= 0.0f) ? acc : 0.01f * acc;
        out[o] = acc;
    }
}

// ---------------- head: avgpool + fc1 + fc2 + VQ + loss ----------------
// conv5 output (bias already applied, no activation): [b][c][49]
__global__ void head_k(const float* __restrict__ conv5,
                       const float* __restrict__ fc1_w, const float* __restrict__ fc1_b,
                       const float* __restrict__ fc2_w, const float* __restrict__ fc2_b,
                       const float* __restrict__ emb,
                       float* __restrict__ loss_out) {
    __shared__ float pooled[BATCH * 64];
    __shared__ float h[BATCH * 16];
    __shared__ float e[BATCH * 16];
    __shared__ float qv[BATCH * 16];
    int tid = threadIdx.x;   // 256 threads

    // AdaptiveAvgPool2d(1): mean over 7x7 per (b, c)
    {
        int b = tid / 64, c = tid % 64;
        const float* p = conv5 + (size_t)(b * 64 + c) * 49;
        float sum = 0.0f;
        #pragma unroll
        for (int i = 0; i < 49; i++) sum += p[i];
        pooled[b * 64 + c] = sum * (1.0f / 49.0f);
    }
    __syncthreads();

    // fc1: [4,64] @ [16,64]^T + b, LeakyReLU
    if (tid < 64) {
        int b = tid / 16, i = tid % 16;
        float s = fc1_b[i];
        #pragma unroll
        for (int c = 0; c < 64; c++) s += pooled[b * 64 + c] * fc1_w[i * 64 + c];
        h[b * 16 + i] = (s >= 0.0f) ? s : 0.01f * s;
    }
    __syncthreads();

    // fc2: [4,16] @ [16,16]^T + b
    if (tid < 64) {
        int b = tid / 16, j = tid % 16;
        float s = fc2_b[j];
        #pragma unroll
        for (int i = 0; i < 16; i++) s += h[b * 16 + i] * fc2_w[j * 16 + i];
        e[b * 16 + j] = s;
    }
    __syncthreads();

    // VQ nearest codebook (DICT = 4)
    if (tid < BATCH) {
        int b = tid;
        float best = 3.402823e38f;
        int bi = 0;
        for (int j = 0; j < 4; j++) {
            float d = 0.0f;
            #pragma unroll
            for (int k = 0; k < 16; k++) {
                float diff = e[b * 16 + k] - emb[j * 16 + k];
                d += diff * diff;
            }
            if (d < best) { best = d; bi = j; }
        }
        #pragma unroll
        for (int k = 0; k < 16; k++) qv[b * 16 + k] = emb[bi * 16 + k];
    }
    __syncthreads();

    if (tid == 0) {
        float s = 0.0f;
        #pragma unroll
        for (int n = 0; n < 64; n++) {
            float d = qv[n] - e[n];
            s += d * d;
        }
        *loss_out = 1.25f * (s * (1.0f / 64.0f));   // q_lat + 0.25 * e_lat
        #pragma unroll
        for (int n = 0; n < 64; n++) g_q[n] = qv[n];
    }
}

// ---------------- big GEMM: flat = q @ W_all, [4,16] x [16, T_TOTAL] ----------------
// Pure HBM streaming: read 2.30 GB of W, write 0.575 GB of output.
// float2 vectorized (rows are 8B-aligned; T_TOTAL % 4 == 2 forbids float4 per-row).
// Streaming cache hints (evict-first): zero reuse, keep L2 from thrashing.
__global__ void __launch_bounds__(256) hyper_gemm_k(const float* __restrict__ W,
                                                    float* __restrict__ out) {
    __shared__ float qs[64];
    if (threadIdx.x < 64) qs[threadIdx.x] = g_q[threadIdx.x];
    __syncthreads();

    long long t2 = (long long)blockIdx.x * blockDim.x + threadIdx.x;
    if (t2 >= T2) return;

    float2 w[16];
    #pragma unroll
    for (int k = 0; k < 16; k++) {
        w[k] = __ldcs((const float2*)(W + (size_t)k * T_TOTAL) + t2);
    }

    #pragma unroll
    for (int b = 0; b < 4; b++) {
        float ax = 0.0f, ay = 0.0f;
        #pragma unroll
        for (int k = 0; k < 16; k++) {
            float qk = qs[b * 16 + k];
            ax = fmaf(qk, w[k].x, ax);
            ay = fmaf(qk, w[k].y, ay);
        }
        __stcs((float2*)(out + (size_t)b * T_TOTAL) + t2, make_float2(ax, ay));
    }
}

// ---------------- launch ----------------
extern "C" void kernel_launch(void* const* d_in, const int* in_sizes, int n_in,
                              void* d_out, int out_size) {
    const float* rgb   = (const float*)d_in[0];
    const float* cw1   = (const float*)d_in[1];
    const float* cb1   = (const float*)d_in[2];
    const float* cw2   = (const float*)d_in[3];
    const float* cb2   = (const float*)d_in[4];
    const float* cw3   = (const float*)d_in[5];
    const float* cb3   = (const float*)d_in[6];
    const float* cw4   = (const float*)d_in[7];
    const float* cb4   = (const float*)d_in[8];
    const float* cw5   = (const float*)d_in[9];
    const float* cb5   = (const float*)d_in[10];
    const float* fc1_w = (const float*)d_in[11];
    const float* fc1_b = (const float*)d_in[12];
    const float* fc2_w = (const float*)d_in[13];
    const float* fc2_b = (const float*)d_in[14];
    const float* emb   = (const float*)d_in[15];
    const float* W_all = (const float*)d_in[16];

    float* out = (float*)d_out;
    float* loss_ptr = out + (size_t)out_size - 1;   // flat first, loss scalar last

    float* bufA;  cudaGetSymbolAddress((void**)&bufA, g_bufA);
    float* bufB;  cudaGetSymbolAddress((void**)&bufB, g_bufB);

    // conv1: 3->4,  224->112, act — 200,704 threads
    convT<3, 4, 224, 112, true, 1, 256><<<784, 256>>>(rgb, cw1, cb1, bufA);
    // conv2: 4->8,  112->56, act — 100,352 threads
    convT<4, 8, 112, 56, true, 1, 256><<<392, 256>>>(bufA, cw2, cb2, bufB);
    // conv3: 8->16, 56->28, act, SPLIT=4 (shuffle) — 200,704 threads
    convT<8, 16, 56, 28, true, 4, 256><<<784, 256>>>(bufB, cw3, cb3, bufA);
    // conv4: 16->32, 28->14, act, SPLIT=4 (shuffle) — 100,352 threads
    convT<16, 32, 28, 14, true, 4, 128><<<784, 128>>>(bufA, cw4, cb4, bufB);
    // conv5: 32->64, 14->7, NO act, SPLIT=8 (shuffle), bias applied — 100,352 threads
    convT<32, 64, 14, 7, false, 8, 128><<<784, 128>>>(bufB, cw5, cb5, bufA);

    // head: pool + fc1 + fc2 + VQ + loss -> writes g_q and loss
    head_k<<<1, 256>>>(bufA, fc1_w, fc1_b, fc2_w, fc2_b, emb, loss_ptr);

    // big streaming GEMM: flat = q @ W_all
    { const int TPB = 256;
      long long nblk = (T2 + TPB - 1) / TPB;
      hyper_gemm_k<<<(unsigned)nblk, TPB>>>(W_all, out); }
}